// round 10
// baseline (speedup 1.0000x reference)
#include <cuda_runtime.h>
#include <cuda_bf16.h>

// Problem constants (reference: B=32, A=4096, P=8388608, E=8)
#define Bn 32
#define An 4096
#define En 8

#define NBLK 64
#define PT 256
#define WPB (PT / 32)             // 8 warps/block
#define NW (NBLK * WPB)           // 512 warps
#define PREFIX (NW * 32)          // 16384 pairs in stage A (1 per lane)
#define WTILE 128                 // fallback tile (32 lanes x int4)
#define POLL_BUDGET 48

// g_done: bit b set => structure b resolved true (eng_big from k_eng, or
// too_close discovered by k_pairs). Reset by a memset node at the head of
// every replay — no in-kernel reset, no cross-replay state.
__device__ unsigned g_done;

__device__ __forceinline__ unsigned poll_u32(const unsigned* p) {
    unsigned v;
    asm volatile("ld.global.cg.u32 %0, [%1];" : "=r"(v) : "l"(p) : "memory");
    return v;
}

// Exact pair test; returns (1u<<n) if too close, else 0.
__device__ __forceinline__ unsigned pair_bit(const float* __restrict__ pos,
                                             const int* __restrict__ elm,
                                             const float* s_rad,
                                             int nb, int i, int j) {
    int ai = nb * An + i;
    int aj = nb * An + j;
    float ax = __ldg(pos + 3 * ai + 0);
    float ay = __ldg(pos + 3 * ai + 1);
    float az = __ldg(pos + 3 * ai + 2);
    float bx = __ldg(pos + 3 * aj + 0);
    float by = __ldg(pos + 3 * aj + 1);
    float bz = __ldg(pos + 3 * aj + 2);
    float rs = s_rad[__ldg(elm + ai)] + s_rad[__ldg(elm + aj)];
    float dx = bx - ax, dy = by - ay, dz = bz - az;
    float sod = dx * dx + dy * dy + dz * dz;
    return (rs * rs >= sod) ? (1u << nb) : 0u;
}

// ---------------------------------------------------------------------------
// K1: per-structure eng_big. Block b (<32) computes eng_max[b], writes
// out[b] = eng_big ? 1 : 0 directly, and seeds g_done. Block 32 zero-fills
// any out elements beyond Bn. Runs after the memset node, before k_pairs.
__global__ void __launch_bounds__(PT)
k_eng(const float* __restrict__ eng,
      const int* __restrict__ elm,
      const float* __restrict__ eng_atm,
      float* __restrict__ out, int out_size) {
    int b = blockIdx.x;
    int tid = threadIdx.x;

    if (b >= Bn) {                       // tail-zero block
        for (int x = Bn + tid; x < out_size; x += PT) out[x] = 0.0f;
        return;
    }

    __shared__ float s_atm[En];
    __shared__ float s_red[PT / 32];
    if (tid < En) s_atm[tid] = eng_atm[tid];
    __syncthreads();

    // 4096 ints / 256 threads = 4 int4 per thread, fully coalesced.
    const int4* row = (const int4*)(elm + b * An);
    float s = 0.f;
    #pragma unroll
    for (int t = 0; t < 4; ++t) {
        int4 e4 = __ldg(row + tid + t * PT);
        s += s_atm[e4.x & 7] + s_atm[e4.y & 7] + s_atm[e4.z & 7] + s_atm[e4.w & 7];
    }
    #pragma unroll
    for (int o = 16; o > 0; o >>= 1)
        s += __shfl_down_sync(0xFFFFFFFFu, s, o);
    if ((tid & 31) == 0) s_red[tid >> 5] = s;
    __syncthreads();

    if (tid == 0) {
        float tot = 0.f;
        #pragma unroll
        for (int w = 0; w < PT / 32; ++w) tot += s_red[w];
        bool big = (__ldg(eng + b) >= tot);
        out[b] = big ? 1.0f : 0.0f;
        if (big) atomicOr(&g_done, 1u << b);   // seed early-exit mask
    }
}

// ---------------------------------------------------------------------------
// K2: pair scan. No global sync anywhere: discoveries are written STRAIGHT
// to out[nb]=1.0f (benign race; k_eng wrote the baseline first, graph-ordered)
// and REDed into g_done only as the exit/skip signal. Each warp exits as soon
// as it sees the mask full — no rendezvous, no ticket, no epilogue.
__global__ void __launch_bounds__(PT)
k_pairs(const float* __restrict__ pos,
        const int* __restrict__ elm,
        const float* __restrict__ radius,
        const int* __restrict__ nn,
        const int* __restrict__ ii,
        const int* __restrict__ jj,
        int P,
        float* __restrict__ out) {
    __shared__ float s_rad[En];

    const int tid  = threadIdx.x;
    const int wid  = tid >> 5;
    const int lane = tid & 31;
    const int gw   = blockIdx.x * WPB + wid;

    if (tid < En) s_rad[tid] = radius[tid];
    __syncthreads();

    // ---- Stage A: one pair per lane from the global prefix.
    {
        int q = gw * 32 + lane;
        unsigned local = 0u;
        int nb = 0;
        if (q < P) {
            nb = __ldg(nn + q);
            local = pair_bit(pos, elm, s_rad, nb, __ldg(ii + q), __ldg(jj + q));
        }
        if (local) out[nb] = 1.0f;                 // direct result store
        unsigned wbits = __reduce_or_sync(0xFFFFFFFFu, local);
        if (wbits && lane == 0) atomicOr(&g_done, wbits);   // RED signal
    }

    // ---- Bounded poll: wait for the global mask to fill (normal case).
    unsigned m = 0u;
    for (int s = 0; s < POLL_BUDGET; ++s) {
        m = poll_u32(&g_done);
        if (m == 0xFFFFFFFFu) return;              // resolved -> exit
    }

    // ---- Fallback (statistically never on this data): scan [PREFIX, P).
    const long long ntiles = ((long long)P - PREFIX + WTILE - 1) / WTILE;
    for (long long t = gw; t < ntiles && m != 0xFFFFFFFFu; t += NW) {
        long long idx = (long long)PREFIX + t * WTILE + lane * 4;
        unsigned local = 0u;
        if (idx + 4 <= (long long)P) {
            int4 n4 = __ldg((const int4*)(nn + idx));
            int4 i4 = __ldg((const int4*)(ii + idx));
            int4 j4 = __ldg((const int4*)(jj + idx));
            int na[4] = {n4.x, n4.y, n4.z, n4.w};
            int ia[4] = {i4.x, i4.y, i4.z, i4.w};
            int ja[4] = {j4.x, j4.y, j4.z, j4.w};
            #pragma unroll
            for (int k = 0; k < 4; ++k) {
                if ((m >> na[k]) & 1u) continue;   // already resolved
                unsigned bit = pair_bit(pos, elm, s_rad, na[k], ia[k], ja[k]);
                if (bit) out[na[k]] = 1.0f;
                local |= bit;
            }
        } else if (idx < (long long)P) {
            for (int k = 0; k < 4; ++k) {
                long long q = idx + k;
                if (q >= (long long)P) break;
                int nb = __ldg(nn + q);
                if ((m >> nb) & 1u) continue;
                unsigned bit = pair_bit(pos, elm, s_rad, nb,
                                        __ldg(ii + q), __ldg(jj + q));
                if (bit) out[nb] = 1.0f;
                local |= bit;
            }
        }
        unsigned wbits = __reduce_or_sync(0xFFFFFFFFu, local) & ~m;
        if (wbits && lane == 0) atomicOr(&g_done, wbits);
        m |= wbits | poll_u32(&g_done);
    }
}

// ---------------------------------------------------------------------------
// Inputs (metadata order): pos[B,A,3] f32, eng[B] f32, elm[B,A] i32,
// radius[E] f32, eng_atm[E] f32, n[P] i32, i[P] i32, j[P] i32.
// Output: float32[B] (0.0 / 1.0).
// Graph: memset(g_done) -> k_eng -> k_pairs. The graph edges ARE the global
// barriers; kernels contain no cross-block sync.
extern "C" void kernel_launch(void* const* d_in, const int* in_sizes, int n_in,
                              void* d_out, int out_size) {
    const float* pos     = (const float*)d_in[0];
    const float* eng     = (const float*)d_in[1];
    const int*   elm     = (const int*)d_in[2];
    const float* radius  = (const float*)d_in[3];
    const float* eng_atm = (const float*)d_in[4];
    const int*   nn      = (const int*)d_in[5];
    const int*   ii      = (const int*)d_in[6];
    const int*   jj      = (const int*)d_in[7];
    int P = in_sizes[5];
    float* out = (float*)d_out;

    void* done_ptr = nullptr;
    cudaGetSymbolAddress(&done_ptr, g_done);       // query only, no alloc
    cudaMemsetAsync(done_ptr, 0, sizeof(unsigned));

    k_eng<<<Bn + 1, PT>>>(eng, elm, eng_atm, out, out_size);
    k_pairs<<<NBLK, PT>>>(pos, elm, radius, nn, ii, jj, P, out);
}

// round 11
// speedup vs baseline: 1.0311x; 1.0311x over previous
#include <cuda_runtime.h>
#include <cuda_bf16.h>

// Problem constants (reference: B=32, A=4096, P=8388608, E=8)
#define Bn 32
#define An 4096
#define En 8
#define NATOMS (Bn * An)

#define PT 256
#define NBLK 64                    // k_pairs blocks
#define WPB (PT / 32)              // 8 warps/block
#define NW (NBLK * WPB)            // 512 warps
#define PREFIX (NW * 32)           // 16384 pairs in stage A (1 per lane)
#define FIN_BLK 32                 // k_finish blocks
#define FIN_W (FIN_BLK * WPB)      // 256 fallback warps
#define WTILE 128                  // fallback tile (32 lanes x int4)

// Scratch (device globals; allocation-free). All state is rewritten
// unconditionally every replay — no cross-replay carryover.
__device__ float4 g_tab[NATOMS];   // (x, y, z, radius[elm]) per atom; 2 MB
__device__ unsigned g_done;        // too-close bits published by k_pairs

__device__ __forceinline__ unsigned poll_u32(const unsigned* p) {
    unsigned v;
    asm volatile("ld.global.cg.u32 %0, [%1];" : "=r"(v) : "l"(p) : "memory");
    return v;
}

// Pair test via the fused table: 2 loads total.
__device__ __forceinline__ unsigned pair_bit_tab(int nb, int i, int j) {
    float4 ta = __ldg(&g_tab[nb * An + i]);
    float4 tb = __ldg(&g_tab[nb * An + j]);
    float dx = tb.x - ta.x, dy = tb.y - ta.y, dz = tb.z - ta.z;
    float sod = dx * dx + dy * dy + dz * dz;
    float rs = ta.w + tb.w;
    return (rs * rs >= sod) ? (1u << nb) : 0u;
}

// ---------------------------------------------------------------------------
// Node 1: k_prep. Block b (<32): eng_max reduction for structure b, writes
// out[b] baseline, AND builds g_tab for its 4096 atoms (elm row is read once
// for both purposes). Block 32: resets g_done (race-free: k_pairs is edge-
// ordered after this kernel) and zero-fills out tail.
__global__ void __launch_bounds__(PT)
k_prep(const float* __restrict__ pos,
       const float* __restrict__ eng,
       const int* __restrict__ elm,
       const float* __restrict__ radius,
       const float* __restrict__ eng_atm,
       float* __restrict__ out, int out_size) {
    int b = blockIdx.x;
    int tid = threadIdx.x;

    if (b >= Bn) {
        if (tid == 0) g_done = 0u;
        for (int x = Bn + tid; x < out_size; x += PT) out[x] = 0.0f;
        return;
    }

    __shared__ float s_atm[En];
    __shared__ float s_rad[En];
    __shared__ float s_red[PT / 32];
    if (tid < En) { s_atm[tid] = eng_atm[tid]; s_rad[tid] = radius[tid]; }
    __syncthreads();

    const int base = b * An;
    float s = 0.f;
    #pragma unroll
    for (int t = 0; t < An / PT; ++t) {         // 16 atoms per thread
        int a = base + tid + t * PT;            // coalesced
        int e = __ldg(elm + a) & 7;
        s += s_atm[e];
        float4 rec;
        rec.x = __ldg(pos + 3 * a + 0);
        rec.y = __ldg(pos + 3 * a + 1);
        rec.z = __ldg(pos + 3 * a + 2);
        rec.w = s_rad[e];
        g_tab[a] = rec;
    }
    #pragma unroll
    for (int o = 16; o > 0; o >>= 1)
        s += __shfl_down_sync(0xFFFFFFFFu, s, o);
    if ((tid & 31) == 0) s_red[tid >> 5] = s;
    __syncthreads();
    if (tid == 0) {
        float tot = 0.f;
        #pragma unroll
        for (int w = 0; w < PT / 32; ++w) tot += s_red[w];
        out[b] = (__ldg(eng + b) >= tot) ? 1.0f : 0.0f;
    }
}

// ---------------------------------------------------------------------------
// Node 2: k_pairs. Stage A ONLY: one pair per lane over the global prefix,
// fused-table gathers, direct out[] store on hit (same-value race, benign),
// one RED per warp, immediate exit. No polling — visibility is absorbed by
// the graph edge to k_finish.
__global__ void __launch_bounds__(PT)
k_pairs(const int* __restrict__ nn,
        const int* __restrict__ ii,
        const int* __restrict__ jj,
        int P,
        float* __restrict__ out) {
    const int tid  = threadIdx.x;
    const int lane = tid & 31;
    const int gw   = blockIdx.x * WPB + (tid >> 5);

    int q = gw * 32 + lane;
    unsigned local = 0u;
    int nb = 0;
    if (q < P) {
        nb = __ldg(nn + q);
        local = pair_bit_tab(nb, __ldg(ii + q), __ldg(jj + q));
    }
    if (local) out[nb] = 1.0f;                  // direct result store
    unsigned wbits = __reduce_or_sync(0xFFFFFFFFu, local);
    if (wbits && lane == 0) atomicOr(&g_done, wbits);
}

// ---------------------------------------------------------------------------
// Node 3: k_finish. Common path: one mask check per block -> return.
// Rare path (mask not full): grid-strided scan of [PREFIX, P) completes the
// too_close computation exactly.
__global__ void __launch_bounds__(PT)
k_finish(const int* __restrict__ nn,
         const int* __restrict__ ii,
         const int* __restrict__ jj,
         int P,
         float* __restrict__ out) {
    __shared__ unsigned s_m;

    const int tid  = threadIdx.x;
    const int wid  = tid >> 5;
    const int lane = tid & 31;

    // Resolved mask = pair bits (g_done) | structures already true in out
    // (covers eng_big baseline and any direct stores).
    if (wid == 0) {
        unsigned pm = (lane == 0) ? poll_u32(&g_done) : 0u;
        pm = __shfl_sync(0xFFFFFFFFu, pm, 0);
        float v = __ldg(out + lane);            // lane b -> out[b], b<32
        unsigned em = __ballot_sync(0xFFFFFFFFu, v != 0.0f);
        if (lane == 0) s_m = pm | em;
    }
    __syncthreads();
    unsigned m = s_m;
    if (m == 0xFFFFFFFFu) return;               // common path: done

    // ---- Fallback: scan remaining pairs [PREFIX, P) exactly.
    const int gw = blockIdx.x * WPB + wid;
    const long long ntiles = ((long long)P - PREFIX + WTILE - 1) / WTILE;
    for (long long t = gw; t < ntiles && m != 0xFFFFFFFFu; t += FIN_W) {
        long long idx = (long long)PREFIX + t * WTILE + lane * 4;
        unsigned local = 0u;
        if (idx + 4 <= (long long)P) {
            int4 n4 = __ldg((const int4*)(nn + idx));
            int4 i4 = __ldg((const int4*)(ii + idx));
            int4 j4 = __ldg((const int4*)(jj + idx));
            int na[4] = {n4.x, n4.y, n4.z, n4.w};
            int ia[4] = {i4.x, i4.y, i4.z, i4.w};
            int ja[4] = {j4.x, j4.y, j4.z, j4.w};
            #pragma unroll
            for (int k = 0; k < 4; ++k) {
                if ((m >> na[k]) & 1u) continue;
                unsigned bit = pair_bit_tab(na[k], ia[k], ja[k]);
                if (bit) out[na[k]] = 1.0f;
                local |= bit;
            }
        } else if (idx < (long long)P) {
            for (int k = 0; k < 4; ++k) {
                long long q = idx + k;
                if (q >= (long long)P) break;
                int nb = __ldg(nn + q);
                if ((m >> nb) & 1u) continue;
                unsigned bit = pair_bit_tab(nb, __ldg(ii + q), __ldg(jj + q));
                if (bit) out[nb] = 1.0f;
                local |= bit;
            }
        }
        unsigned wbits = __reduce_or_sync(0xFFFFFFFFu, local) & ~m;
        if (wbits && lane == 0) atomicOr(&g_done, wbits);
        m |= wbits | poll_u32(&g_done);
    }
}

// ---------------------------------------------------------------------------
// Inputs (metadata order): pos[B,A,3] f32, eng[B] f32, elm[B,A] i32,
// radius[E] f32, eng_atm[E] f32, n[P] i32, i[P] i32, j[P] i32.
// Output: float32[B] (0.0 / 1.0).
// Graph: k_prep -> k_pairs -> k_finish. Edges are the only global barriers.
extern "C" void kernel_launch(void* const* d_in, const int* in_sizes, int n_in,
                              void* d_out, int out_size) {
    const float* pos     = (const float*)d_in[0];
    const float* eng     = (const float*)d_in[1];
    const int*   elm     = (const int*)d_in[2];
    const float* radius  = (const float*)d_in[3];
    const float* eng_atm = (const float*)d_in[4];
    const int*   nn      = (const int*)d_in[5];
    const int*   ii      = (const int*)d_in[6];
    const int*   jj      = (const int*)d_in[7];
    int P = in_sizes[5];
    float* out = (float*)d_out;

    k_prep<<<Bn + 1, PT>>>(pos, eng, elm, radius, eng_atm, out, out_size);
    k_pairs<<<NBLK, PT>>>(nn, ii, jj, P, out);
    k_finish<<<FIN_BLK, PT>>>(nn, ii, jj, P, out);
}

// round 12
// speedup vs baseline: 1.0408x; 1.0094x over previous
#include <cuda_runtime.h>
#include <cuda_bf16.h>

// Problem constants (reference: B=32, A=4096, P=8388608, E=8)
#define Bn 32
#define An 4096
#define En 8

#define PT 256
#define NBLK 64                    // k_pairs blocks
#define WPB (PT / 32)              // 8 warps/block
#define NW (NBLK * WPB)            // 512 warps
#define PREFIX (NW * 32)           // 16384 pairs in stage A (1 per lane)
#define FIN_BLK 32                 // k_finish blocks
#define FIN_W (FIN_BLK * WPB)      // 256 fallback warps
#define WTILE 128                  // fallback tile (32 lanes x int4)

// Persistent scratch: rewritten every replay (k_prep resets), so no
// cross-replay state leaks.
__device__ unsigned g_done;        // too-close bits published by k_pairs

__device__ __forceinline__ unsigned poll_u32(const unsigned* p) {
    unsigned v;
    asm volatile("ld.global.cg.u32 %0, [%1];" : "=r"(v) : "l"(p) : "memory");
    return v;
}

// Exact pair test with raw gathers; returns (1u<<n) if too close, else 0.
__device__ __forceinline__ unsigned pair_bit(const float* __restrict__ pos,
                                             const int* __restrict__ elm,
                                             const float* s_rad,
                                             int nb, int i, int j) {
    int ai = nb * An + i;
    int aj = nb * An + j;
    float ax = __ldg(pos + 3 * ai + 0);
    float ay = __ldg(pos + 3 * ai + 1);
    float az = __ldg(pos + 3 * ai + 2);
    float bx = __ldg(pos + 3 * aj + 0);
    float by = __ldg(pos + 3 * aj + 1);
    float bz = __ldg(pos + 3 * aj + 2);
    float rs = s_rad[__ldg(elm + ai) & 7] + s_rad[__ldg(elm + aj) & 7];
    float dx = bx - ax, dy = by - ay, dz = bz - az;
    float sod = dx * dx + dy * dy + dz * dz;
    return (rs * rs >= sod) ? (1u << nb) : 0u;
}

// ---------------------------------------------------------------------------
// Node 1: k_prep. Block b (<32): eng_max reduction for structure b, writes
// the out[b] baseline. Block 32: resets g_done (edge-ordered before k_pairs'
// REDs) and zero-fills the out tail. NO table build (dead weight at this
// scale — R11 measured it at 7.5us).
__global__ void __launch_bounds__(PT)
k_prep(const float* __restrict__ eng,
       const int* __restrict__ elm,
       const float* __restrict__ eng_atm,
       float* __restrict__ out, int out_size) {
    int b = blockIdx.x;
    int tid = threadIdx.x;

    if (b >= Bn) {
        if (tid == 0) g_done = 0u;
        for (int x = Bn + tid; x < out_size; x += PT) out[x] = 0.0f;
        return;
    }

    __shared__ float s_atm[En];
    __shared__ float s_red[PT / 32];
    if (tid < En) s_atm[tid] = eng_atm[tid];
    __syncthreads();

    // 4096 ints / 256 threads = 4 int4 loads per thread, fully coalesced.
    const int4* row = (const int4*)(elm + b * An);
    float s = 0.f;
    #pragma unroll
    for (int t = 0; t < An / (PT * 4); ++t) {
        int4 e4 = __ldg(row + tid + t * PT);
        s += s_atm[e4.x & 7] + s_atm[e4.y & 7] + s_atm[e4.z & 7] + s_atm[e4.w & 7];
    }
    #pragma unroll
    for (int o = 16; o > 0; o >>= 1)
        s += __shfl_down_sync(0xFFFFFFFFu, s, o);
    if ((tid & 31) == 0) s_red[tid >> 5] = s;
    __syncthreads();
    if (tid == 0) {
        float tot = 0.f;
        #pragma unroll
        for (int w = 0; w < PT / 32; ++w) tot += s_red[w];
        out[b] = (__ldg(eng + b) >= tot) ? 1.0f : 0.0f;
    }
}

// ---------------------------------------------------------------------------
// Node 2: k_pairs. Stage A only: one pair per lane over the global prefix,
// raw gathers, direct out[] store on hit (same-value race, benign), one RED
// per warp, immediate exit. Zero polling — the graph edge to k_finish
// absorbs RED visibility latency.
__global__ void __launch_bounds__(PT)
k_pairs(const float* __restrict__ pos,
        const int* __restrict__ elm,
        const float* __restrict__ radius,
        const int* __restrict__ nn,
        const int* __restrict__ ii,
        const int* __restrict__ jj,
        int P,
        float* __restrict__ out) {
    __shared__ float s_rad[En];
    const int tid  = threadIdx.x;
    const int lane = tid & 31;
    const int gw   = blockIdx.x * WPB + (tid >> 5);

    if (tid < En) s_rad[tid] = radius[tid];
    __syncthreads();

    int q = gw * 32 + lane;
    unsigned local = 0u;
    int nb = 0;
    if (q < P) {
        nb = __ldg(nn + q);
        local = pair_bit(pos, elm, s_rad, nb, __ldg(ii + q), __ldg(jj + q));
    }
    if (local) out[nb] = 1.0f;                  // direct result store
    unsigned wbits = __reduce_or_sync(0xFFFFFFFFu, local);
    if (wbits && lane == 0) atomicOr(&g_done, wbits);
}

// ---------------------------------------------------------------------------
// Node 3: k_finish. Common path: one mask check per block -> return.
// Rare path: grid-strided exact scan of [PREFIX, P).
__global__ void __launch_bounds__(PT)
k_finish(const float* __restrict__ pos,
         const int* __restrict__ elm,
         const float* __restrict__ radius,
         const int* __restrict__ nn,
         const int* __restrict__ ii,
         const int* __restrict__ jj,
         int P,
         float* __restrict__ out) {
    __shared__ unsigned s_m;
    __shared__ float s_rad[En];

    const int tid  = threadIdx.x;
    const int wid  = tid >> 5;
    const int lane = tid & 31;

    // Resolved mask = pair bits | structures already true in out
    // (covers the eng_big baseline and direct stores).
    if (wid == 0) {
        unsigned pm = (lane == 0) ? poll_u32(&g_done) : 0u;
        pm = __shfl_sync(0xFFFFFFFFu, pm, 0);
        float v = __ldg(out + lane);            // lane b -> out[b]
        unsigned em = __ballot_sync(0xFFFFFFFFu, v != 0.0f);
        if (lane == 0) s_m = pm | em;
    }
    if (tid < En) s_rad[tid] = radius[tid];
    __syncthreads();
    unsigned m = s_m;
    if (m == 0xFFFFFFFFu) return;               // common path

    // ---- Fallback: exact scan of the remaining pairs.
    const int gw = blockIdx.x * WPB + wid;
    const long long ntiles = ((long long)P - PREFIX + WTILE - 1) / WTILE;
    for (long long t = gw; t < ntiles && m != 0xFFFFFFFFu; t += FIN_W) {
        long long idx = (long long)PREFIX + t * WTILE + lane * 4;
        unsigned local = 0u;
        if (idx + 4 <= (long long)P) {
            int4 n4 = __ldg((const int4*)(nn + idx));
            int4 i4 = __ldg((const int4*)(ii + idx));
            int4 j4 = __ldg((const int4*)(jj + idx));
            int na[4] = {n4.x, n4.y, n4.z, n4.w};
            int ia[4] = {i4.x, i4.y, i4.z, i4.w};
            int ja[4] = {j4.x, j4.y, j4.z, j4.w};
            #pragma unroll
            for (int k = 0; k < 4; ++k) {
                if ((m >> na[k]) & 1u) continue;
                unsigned bit = pair_bit(pos, elm, s_rad, na[k], ia[k], ja[k]);
                if (bit) out[na[k]] = 1.0f;
                local |= bit;
            }
        } else if (idx < (long long)P) {
            for (int k = 0; k < 4; ++k) {
                long long q = idx + k;
                if (q >= (long long)P) break;
                int nb = __ldg(nn + q);
                if ((m >> nb) & 1u) continue;
                unsigned bit = pair_bit(pos, elm, s_rad, nb,
                                        __ldg(ii + q), __ldg(jj + q));
                if (bit) out[nb] = 1.0f;
                local |= bit;
            }
        }
        unsigned wbits = __reduce_or_sync(0xFFFFFFFFu, local) & ~m;
        if (wbits && lane == 0) atomicOr(&g_done, wbits);
        m |= wbits | poll_u32(&g_done);
    }
}

// ---------------------------------------------------------------------------
// Inputs (metadata order): pos[B,A,3] f32, eng[B] f32, elm[B,A] i32,
// radius[E] f32, eng_atm[E] f32, n[P] i32, i[P] i32, j[P] i32.
// Output: float32[B] (0.0 / 1.0).
// Graph: k_prep -> k_pairs -> k_finish; edges are the only global barriers.
extern "C" void kernel_launch(void* const* d_in, const int* in_sizes, int n_in,
                              void* d_out, int out_size) {
    const float* pos     = (const float*)d_in[0];
    const float* eng     = (const float*)d_in[1];
    const int*   elm     = (const int*)d_in[2];
    const float* radius  = (const float*)d_in[3];
    const float* eng_atm = (const float*)d_in[4];
    const int*   nn      = (const int*)d_in[5];
    const int*   ii      = (const int*)d_in[6];
    const int*   jj      = (const int*)d_in[7];
    int P = in_sizes[5];
    float* out = (float*)d_out;

    k_prep<<<Bn + 1, PT>>>(eng, elm, eng_atm, out, out_size);
    k_pairs<<<NBLK, PT>>>(pos, elm, radius, nn, ii, jj, P, out);
    k_finish<<<FIN_BLK, PT>>>(pos, elm, radius, nn, ii, jj, P, out);
}

// round 13
// speedup vs baseline: 1.2117x; 1.1642x over previous
#include <cuda_runtime.h>
#include <cuda_bf16.h>

// Problem constants (reference: B=32, A=4096, P=8388608, E=8)
#define Bn 32
#define An 4096
#define En 8

#define PT 256
#define ENG_BLK Bn                 // blocks 0..31: engmax
#define PAIR_BLK 64                // blocks 32..95: pair scan
#define K1_BLK (ENG_BLK + PAIR_BLK)
#define WPB (PT / 32)              // 8 warps/block
#define NPW (PAIR_BLK * WPB)       // 512 pair warps
#define PREFIX (NPW * 32)          // 16384 pairs in stage A (1 per lane)
#define WTILE 128                  // fallback tile (32 lanes x int4)

// g_done: bit b set => out[b] = 1 (eng_big OR too_close). Zero at module
// load; K2 resets it to 0 after consuming it, and K2 is stream-ordered
// before the next replay's K1 — so every replay starts from 0.
__device__ unsigned g_done;

__device__ __forceinline__ unsigned poll_u32(const unsigned* p) {
    unsigned v;
    asm volatile("ld.global.cg.u32 %0, [%1];" : "=r"(v) : "l"(p) : "memory");
    return v;
}

// Exact pair test; returns (1u<<n) if too close, else 0.
__device__ __forceinline__ unsigned pair_bit(const float* __restrict__ pos,
                                             const int* __restrict__ elm,
                                             const float* s_rad,
                                             int nb, int i, int j) {
    int ai = nb * An + i;
    int aj = nb * An + j;
    float ax = __ldg(pos + 3 * ai + 0);
    float ay = __ldg(pos + 3 * ai + 1);
    float az = __ldg(pos + 3 * ai + 2);
    float bx = __ldg(pos + 3 * aj + 0);
    float by = __ldg(pos + 3 * aj + 1);
    float bz = __ldg(pos + 3 * aj + 2);
    float rs = s_rad[__ldg(elm + ai) & 7] + s_rad[__ldg(elm + aj) & 7];
    float dx = bx - ax, dy = by - ay, dz = bz - az;
    float sod = dx * dx + dy * dy + dz * dz;
    return (rs * rs >= sod) ? (1u << nb) : 0u;
}

// ---------------------------------------------------------------------------
// K1: engmax blocks and pair blocks run CONCURRENTLY (independent inputs,
// same output monoid: OR into g_done). No out[] writes here.
__global__ void __launch_bounds__(PT)
k_scan(const float* __restrict__ pos,
       const float* __restrict__ eng,
       const int* __restrict__ elm,
       const float* __restrict__ radius,
       const float* __restrict__ eng_atm,
       const int* __restrict__ nn,
       const int* __restrict__ ii,
       const int* __restrict__ jj,
       int P) {
    const int tid = threadIdx.x;
    const int bid = blockIdx.x;

    if (bid < ENG_BLK) {
        // ---- engmax for structure `bid` ----
        __shared__ float s_atm[En];
        __shared__ float s_red[PT / 32];
        if (tid < En) s_atm[tid] = eng_atm[tid];
        __syncthreads();

        const int4* row = (const int4*)(elm + bid * An);
        float s = 0.f;
        #pragma unroll
        for (int t = 0; t < An / (PT * 4); ++t) {   // 4 int4 per thread
            int4 e4 = __ldg(row + tid + t * PT);
            s += s_atm[e4.x & 7] + s_atm[e4.y & 7]
               + s_atm[e4.z & 7] + s_atm[e4.w & 7];
        }
        #pragma unroll
        for (int o = 16; o > 0; o >>= 1)
            s += __shfl_down_sync(0xFFFFFFFFu, s, o);
        if ((tid & 31) == 0) s_red[tid >> 5] = s;
        __syncthreads();
        if (tid == 0) {
            float tot = 0.f;
            #pragma unroll
            for (int w = 0; w < PT / 32; ++w) tot += s_red[w];
            if (__ldg(eng + bid) >= tot)
                atomicOr(&g_done, 1u << bid);       // RED
        }
        return;
    }

    // ---- pair scan: one pair per lane over the global prefix ----
    __shared__ float s_rad[En];
    const int lane = tid & 31;
    const int gw = (bid - ENG_BLK) * WPB + (tid >> 5);

    if (tid < En) s_rad[tid] = radius[tid];
    __syncthreads();

    int q = gw * 32 + lane;
    unsigned local = 0u;
    if (q < P)
        local = pair_bit(pos, elm, s_rad, __ldg(nn + q),
                         __ldg(ii + q), __ldg(jj + q));
    unsigned wbits = __reduce_or_sync(0xFFFFFFFFu, local);
    if (wbits && lane == 0) atomicOr(&g_done, wbits);   // RED
}

// ---------------------------------------------------------------------------
// K2: single block. Graph edge => all K1 REDs visible. Reads the mask once,
// writes the float32 output, resets g_done for the next replay. Fallback
// (mask not full) completes the computation exactly in this block.
__global__ void __launch_bounds__(PT)
k_finish(const float* __restrict__ pos,
         const float* __restrict__ eng,
         const int* __restrict__ elm,
         const float* __restrict__ radius,
         const float* __restrict__ eng_atm,
         const int* __restrict__ nn,
         const int* __restrict__ ii,
         const int* __restrict__ jj,
         int P,
         float* __restrict__ out, int out_size) {
    __shared__ unsigned s_m;
    __shared__ float s_rad[En];

    const int tid  = threadIdx.x;
    const int wid  = tid >> 5;
    const int lane = tid & 31;

    if (tid == 0) s_m = poll_u32(&g_done);
    if (tid < En) s_rad[tid] = radius[tid];
    __syncthreads();
    unsigned m = s_m;

    if (m != 0xFFFFFFFFu) {
        // ---- Fallback A: exact scan of remaining pairs [PREFIX, P).
        const long long ntiles = ((long long)P - PREFIX + WTILE - 1) / WTILE;
        for (long long t = wid; t < ntiles; t += WPB) {
            if (m == 0xFFFFFFFFu) break;
            long long idx = (long long)PREFIX + t * WTILE + lane * 4;
            unsigned local = 0u;
            if (idx + 4 <= (long long)P) {
                int4 n4 = __ldg((const int4*)(nn + idx));
                int4 i4 = __ldg((const int4*)(ii + idx));
                int4 j4 = __ldg((const int4*)(jj + idx));
                int na[4] = {n4.x, n4.y, n4.z, n4.w};
                int ia[4] = {i4.x, i4.y, i4.z, i4.w};
                int ja[4] = {j4.x, j4.y, j4.z, j4.w};
                #pragma unroll
                for (int k = 0; k < 4; ++k)
                    if (!((m >> na[k]) & 1u))
                        local |= pair_bit(pos, elm, s_rad, na[k], ia[k], ja[k]);
            } else if (idx < (long long)P) {
                for (int k = 0; k < 4; ++k) {
                    long long q = idx + k;
                    if (q >= (long long)P) break;
                    int nb = __ldg(nn + q);
                    if (!((m >> nb) & 1u))
                        local |= pair_bit(pos, elm, s_rad, nb,
                                          __ldg(ii + q), __ldg(jj + q));
                }
            }
            unsigned wbits = __reduce_or_sync(0xFFFFFFFFu, local) & ~m;
            if (wbits && lane == 0) atomicOr(&s_m, wbits);  // smem atomic
            m |= wbits;
            if ((t & 63) == 63) {                  // periodic block-wide refresh
                __syncthreads();
                m = s_m;
            }
        }
        __syncthreads();
        m = s_m;

        // ---- Fallback B: engmax for still-unset structures (warp w handles
        // structures w, w+8, w+16, w+24).
        for (int sb = wid; sb < Bn; sb += WPB) {
            if ((m >> sb) & 1u) continue;
            float av = __ldg(eng_atm + (lane & (En - 1)));
            const int4* row = (const int4*)(elm + sb * An);
            float s = 0.f;
            #pragma unroll 4
            for (int t2 = lane; t2 < An / 4; t2 += 32) {
                int4 e4 = __ldg(row + t2);
                s += __shfl_sync(0xFFFFFFFFu, av, e4.x & 7);
                s += __shfl_sync(0xFFFFFFFFu, av, e4.y & 7);
                s += __shfl_sync(0xFFFFFFFFu, av, e4.z & 7);
                s += __shfl_sync(0xFFFFFFFFu, av, e4.w & 7);
            }
            #pragma unroll
            for (int o = 16; o > 0; o >>= 1)
                s += __shfl_down_sync(0xFFFFFFFFu, s, o);
            if (lane == 0 && __ldg(eng + sb) >= s)
                atomicOr(&s_m, 1u << sb);
        }
        __syncthreads();
        m = s_m;
    }

    // ---- Write output and reset the flag for the next replay.
    for (int b = tid; b < out_size; b += PT)
        out[b] = (b < Bn) ? (float)((m >> b) & 1u) : 0.0f;
    if (tid == 0) g_done = 0u;     // single writer, post-read; next K1 is
                                   // stream-ordered after this kernel
}

// ---------------------------------------------------------------------------
// Inputs (metadata order): pos[B,A,3] f32, eng[B] f32, elm[B,A] i32,
// radius[E] f32, eng_atm[E] f32, n[P] i32, i[P] i32, j[P] i32.
// Output: float32[B] (0.0 / 1.0).
// Graph: k_scan -> k_finish. The edge is the only global barrier.
extern "C" void kernel_launch(void* const* d_in, const int* in_sizes, int n_in,
                              void* d_out, int out_size) {
    const float* pos     = (const float*)d_in[0];
    const float* eng     = (const float*)d_in[1];
    const int*   elm     = (const int*)d_in[2];
    const float* radius  = (const float*)d_in[3];
    const float* eng_atm = (const float*)d_in[4];
    const int*   nn      = (const int*)d_in[5];
    const int*   ii      = (const int*)d_in[6];
    const int*   jj      = (const int*)d_in[7];
    int P = in_sizes[5];
    float* out = (float*)d_out;

    k_scan<<<K1_BLK, PT>>>(pos, eng, elm, radius, eng_atm, nn, ii, jj, P);
    k_finish<<<1, PT>>>(pos, eng, elm, radius, eng_atm, nn, ii, jj, P,
                        out, out_size);
}